// round 8
// baseline (speedup 1.0000x reference)
#include <cuda_runtime.h>

typedef unsigned long long u64;

#define THREADS 128
#define NPTS 2                          // points per thread
#define PTS_PER_BLOCK (THREADS * NPTS)
#define HIDDEN 16
#define NLAYERS 8

// Single packed constant bank. Warp-uniform 64-bit reads -> ULDC/LDCU on the
// dedicated uniform-constant port (floor=1/SMSP), zero L1 traffic.
// (128-bit reads are avoided: LDC.128 to GPRs is the half-rate port, floor=8.)
#define OFF_WIN  0      // [j][c], 32
#define OFF_BIN  32     // [j], 16
#define OFF_WOUT 48     // [j][k], 48
#define OFF_WH   96     // [l][j][k], 2048
#define CW_TOTAL 2144
__constant__ __align__(16) float cW[CW_TOTAL];

// ---------- f32x2 packed-math helpers (sm_103a) ----------
__device__ __forceinline__ u64 pack2(float lo, float hi) {
    u64 r; asm("mov.b64 %0, {%1, %2};" : "=l"(r) : "f"(lo), "f"(hi)); return r;
}
__device__ __forceinline__ void unpack2(u64 a, float& lo, float& hi) {
    asm("mov.b64 {%0, %1}, %2;" : "=f"(lo), "=f"(hi) : "l"(a));
}
__device__ __forceinline__ u64 ffma2(u64 a, u64 b, u64 c) {
    u64 d; asm("fma.rn.f32x2 %0, %1, %2, %3;" : "=l"(d) : "l"(a), "l"(b), "l"(c)); return d;
}
__device__ __forceinline__ u64 fmul2(u64 a, u64 b) {
    u64 d; asm("mul.rn.f32x2 %0, %1, %2;" : "=l"(d) : "l"(a), "l"(b)); return d;
}
__device__ __forceinline__ u64 fadd2(u64 a, u64 b) {
    u64 d; asm("add.rn.f32x2 %0, %1, %2;" : "=l"(d) : "l"(a), "l"(b)); return d;
}
__device__ __forceinline__ float tanh_hw(float x) {
    float r; asm("tanh.approx.f32 %0, %1;" : "=f"(r) : "f"(x)); return r;
}
__device__ __forceinline__ u64 tanh2(u64 a) {
    float lo, hi; unpack2(a, lo, hi);
    return pack2(tanh_hw(lo), tanh_hw(hi));
}
__device__ __forceinline__ float sigmoid_hw(float x) {
    return fmaf(tanh_hw(0.5f * x), 0.5f, 0.5f);
}
// Horizontal sum of a j-pair: (a0+a1, b0+b1).
__device__ __forceinline__ u64 hsum_pair(u64 acc_a, u64 acc_b) {
    float a0, a1, b0, b1;
    unpack2(acc_a, a0, a1);
    unpack2(acc_b, b0, b1);
    return fadd2(pack2(a0, b0), pack2(a1, b1));
}

// Parallel staging: one element per thread, one LDG round (~2 us).
// Identical data every call -> deterministic replays.
__global__ void stage_weights(const float* __restrict__ W_in,
                              const float* __restrict__ b_in,
                              const float* __restrict__ W_h,
                              const float* __restrict__ W_out,
                              float* __restrict__ dst)
{
    int i = blockIdx.x * blockDim.x + threadIdx.x;
    if (i < 32)            dst[OFF_WIN + i] = W_in[i];
    else if (i < 48)       dst[OFF_BIN + i - 32] = b_in[i - 32];
    else if (i < 96)       dst[OFF_WOUT + i - 48] = W_out[i - 48];
    else if (i < 96 + NLAYERS * 256) dst[i] = W_h[i - 96];
}

__global__ void __launch_bounds__(THREADS, 5)
mlp_kernel(const float* __restrict__ x,
           float* __restrict__ out)
{
    const int tid = threadIdx.x;
    const int base = blockIdx.x * PTS_PER_BLOCK + tid;

    const float2* __restrict__ xp = (const float2*)x;
    float2 xv[NPTS];
    #pragma unroll
    for (int p = 0; p < NPTS; p++) xv[p] = xp[base + p * THREADS];

    // h[p][kk] holds the activation pair (h_{2kk}, h_{2kk+1})
    u64 h[NPTS][8];

    // ---- input layer: h_j = tanh(x0*W[j][0] + x1*W[j][1] + b_j) ----
    {
        const u64* __restrict__ win = (const u64*)&cW[OFF_WIN]; // (W[j][0],W[j][1])
        const u64* __restrict__ bb  = (const u64*)&cW[OFF_BIN]; // (b_{2jj},b_{2jj+1})
        #pragma unroll
        for (int p = 0; p < NPTS; p++) {
            u64 xpair = pack2(xv[p].x, xv[p].y);
            #pragma unroll
            for (int jj = 0; jj < 8; jj++) {
                u64 ma = fmul2(xpair, win[2 * jj]);
                u64 mb = fmul2(xpair, win[2 * jj + 1]);
                u64 s = fadd2(hsum_pair(ma, mb), bb[jj]);
                h[p][jj] = tanh2(s);
            }
        }
    }

    // ---- 8 hidden layers: h' = tanh(h @ W^T) ----
    // Fully unrolled: all weight offsets compile-time -> ptxas can hoist
    // next layer's ULDCs into the current layer's tanh latency shadow.
    #pragma unroll
    for (int l = 0; l < NLAYERS; l++) {
        const u64* __restrict__ wl = (const u64*)&cW[OFF_WH + l * 256]; // [j*8+kk]
        u64 hn[NPTS][8];
        #pragma unroll
        for (int jj = 0; jj < 8; jj++) {
            const u64* __restrict__ wa = wl + (2 * jj) * 8;
            const u64* __restrict__ wb = wl + (2 * jj + 1) * 8;
            #pragma unroll
            for (int p = 0; p < NPTS; p++) {
                u64 acc_a = fmul2(h[p][0], wa[0]);
                u64 acc_b = fmul2(h[p][0], wb[0]);
                #pragma unroll
                for (int kk = 1; kk < 8; kk++) {
                    acc_a = ffma2(h[p][kk], wa[kk], acc_a);
                    acc_b = ffma2(h[p][kk], wb[kk], acc_b);
                }
                hn[p][jj] = tanh2(hsum_pair(acc_a, acc_b));
            }
        }
        #pragma unroll
        for (int p = 0; p < NPTS; p++)
            #pragma unroll
            for (int jj = 0; jj < 8; jj++) h[p][jj] = hn[p][jj];
    }

    // ---- output layer: sigmoid(h @ W_out^T), 16 -> 3 ----
    #pragma unroll
    for (int p = 0; p < NPTS; p++) {
        int pt = base + p * THREADS;
        const u64* __restrict__ wo = (const u64*)&cW[OFF_WOUT];  // [j*8 + kk]
        #pragma unroll
        for (int j = 0; j < 3; j++) {
            u64 acc = fmul2(h[p][0], wo[j * 8]);
            #pragma unroll
            for (int kk = 1; kk < 8; kk++)
                acc = ffma2(h[p][kk], wo[j * 8 + kk], acc);
            float a0, a1; unpack2(acc, a0, a1);
            out[pt * 3 + j] = sigmoid_hw(a0 + a1);
        }
    }
}

extern "C" void kernel_launch(void* const* d_in, const int* in_sizes, int n_in,
                              void* d_out, int out_size) {
    const float* x     = (const float*)d_in[0];
    const float* W_in  = (const float*)d_in[1];
    const float* b_in  = (const float*)d_in[2];
    const float* W_h   = (const float*)d_in[3];
    const float* W_out = (const float*)d_in[4];
    float* out = (float*)d_out;

    void* cw_addr = nullptr;
    cudaGetSymbolAddress(&cw_addr, cW);

    stage_weights<<<(CW_TOTAL + 255) / 256, 256>>>(W_in, b_in, W_h, W_out,
                                                   (float*)cw_addr);

    int n_points = in_sizes[0] / 2;               // x is [N,2]
    int blocks = n_points / PTS_PER_BLOCK;        // 4194304 / 256 = 16384, exact
    mlp_kernel<<<blocks, THREADS>>>(x, out);
}

// round 9
// speedup vs baseline: 1.1168x; 1.1168x over previous
#include <cuda_runtime.h>

typedef unsigned long long u64;

#define THREADS 128
#define NPTS 2                          // points per thread
#define PTS_PER_BLOCK (THREADS * NPTS)
#define HIDDEN 16
#define NLAYERS 8

// Single packed constant bank. Warp-uniform 64-bit reads -> ULDC/LDCU on the
// dedicated uniform-constant port (floor=1/SMSP), zero L1 traffic.
// (128-bit constant reads regress: LDC.128 to GPRs is half-rate, floor=8.)
#define OFF_WIN  0      // [j][c], 32
#define OFF_BIN  32     // [j], 16
#define OFF_WOUT 48     // [j][k], 48
#define OFF_WH   96     // [l][j][k], 2048
#define CW_TOTAL 2144
__constant__ __align__(16) float cW[CW_TOTAL];

// ---------- f32x2 packed-math helpers (sm_103a) ----------
__device__ __forceinline__ u64 pack2(float lo, float hi) {
    u64 r; asm("mov.b64 %0, {%1, %2};" : "=l"(r) : "f"(lo), "f"(hi)); return r;
}
__device__ __forceinline__ void unpack2(u64 a, float& lo, float& hi) {
    asm("mov.b64 {%0, %1}, %2;" : "=f"(lo), "=f"(hi) : "l"(a));
}
__device__ __forceinline__ u64 ffma2(u64 a, u64 b, u64 c) {
    u64 d; asm("fma.rn.f32x2 %0, %1, %2, %3;" : "=l"(d) : "l"(a), "l"(b), "l"(c)); return d;
}
__device__ __forceinline__ u64 fmul2(u64 a, u64 b) {
    u64 d; asm("mul.rn.f32x2 %0, %1, %2;" : "=l"(d) : "l"(a), "l"(b)); return d;
}
__device__ __forceinline__ float tanh_hw(float x) {
    float r; asm("tanh.approx.f32 %0, %1;" : "=f"(r) : "f"(x)); return r;
}
__device__ __forceinline__ float sigmoid_hw(float x) {
    return fmaf(tanh_hw(0.5f * x), 0.5f, 0.5f);
}

// Parallel staging: one element per thread, one LDG round (~2 us).
// Identical data every call -> deterministic replays.
__global__ void stage_weights(const float* __restrict__ W_in,
                              const float* __restrict__ b_in,
                              const float* __restrict__ W_h,
                              const float* __restrict__ W_out,
                              float* __restrict__ dst)
{
    int i = blockIdx.x * blockDim.x + threadIdx.x;
    if (i < 32)            dst[OFF_WIN + i] = W_in[i];
    else if (i < 48)       dst[OFF_BIN + i - 32] = b_in[i - 32];
    else if (i < 96)       dst[OFF_WOUT + i - 48] = W_out[i - 48];
    else if (i < 96 + NLAYERS * 256) dst[i] = W_h[i - 96];
}

__global__ void __launch_bounds__(THREADS, 5)
mlp_kernel(const float* __restrict__ x,
           float* __restrict__ out)
{
    const int tid = threadIdx.x;
    const int base = blockIdx.x * PTS_PER_BLOCK + tid;

    const float2* __restrict__ xp = (const float2*)x;
    float2 xv[NPTS];
    #pragma unroll
    for (int p = 0; p < NPTS; p++) xv[p] = xp[base + p * THREADS];

    // h[p][kk] holds the activation pair (h_{2kk}, h_{2kk+1})
    u64 h[NPTS][8];

    // ---- input layer: h_j = tanh(x0*W[j][0] + x1*W[j][1] + b_j) ----
    {
        const u64* __restrict__ win = (const u64*)&cW[OFF_WIN]; // (W[j][0],W[j][1])
        #pragma unroll
        for (int p = 0; p < NPTS; p++) {
            u64 xpair = pack2(xv[p].x, xv[p].y);
            #pragma unroll
            for (int jj = 0; jj < 8; jj++) {
                u64 ma = fmul2(xpair, win[2 * jj]);
                u64 mb = fmul2(xpair, win[2 * jj + 1]);
                float a0, a1, b0, b1;
                unpack2(ma, a0, a1);
                unpack2(mb, b0, b1);
                float sa = a0 + a1 + cW[OFF_BIN + 2 * jj];
                float sb = b0 + b1 + cW[OFF_BIN + 2 * jj + 1];
                h[p][jj] = pack2(tanh_hw(sa), tanh_hw(sb));
            }
        }
    }

    // ---- 8 hidden layers: h' = tanh(h @ W^T) ----
    // Rolled layer loop (small body, I$-resident); u64 uniform-port reads.
    #pragma unroll 1
    for (int l = 0; l < NLAYERS; l++) {
        const u64* __restrict__ wl = (const u64*)&cW[OFF_WH + l * 256]; // [j*8+kk]
        u64 hn[NPTS][8];
        #pragma unroll
        for (int jj = 0; jj < 8; jj++) {
            const u64* __restrict__ wa = wl + (2 * jj) * 8;
            const u64* __restrict__ wb = wl + (2 * jj + 1) * 8;
            #pragma unroll
            for (int p = 0; p < NPTS; p++) {
                u64 acc_a = fmul2(h[p][0], wa[0]);
                u64 acc_b = fmul2(h[p][0], wb[0]);
                #pragma unroll
                for (int kk = 1; kk < 8; kk++) {
                    acc_a = ffma2(h[p][kk], wa[kk], acc_a);
                    acc_b = ffma2(h[p][kk], wb[kk], acc_b);
                }
                // Horizontal sums as scalar FADDs on the free pair halves;
                // only the tanh outputs are packed (fresh MUFU dests coalesce).
                float a0, a1, b0, b1;
                unpack2(acc_a, a0, a1);
                unpack2(acc_b, b0, b1);
                hn[p][jj] = pack2(tanh_hw(a0 + a1), tanh_hw(b0 + b1));
            }
        }
        #pragma unroll
        for (int p = 0; p < NPTS; p++)
            #pragma unroll
            for (int jj = 0; jj < 8; jj++) h[p][jj] = hn[p][jj];
    }

    // ---- output layer: sigmoid(h @ W_out^T), 16 -> 3 ----
    #pragma unroll
    for (int p = 0; p < NPTS; p++) {
        int pt = base + p * THREADS;
        const u64* __restrict__ wo = (const u64*)&cW[OFF_WOUT];  // [j*8 + kk]
        #pragma unroll
        for (int j = 0; j < 3; j++) {
            u64 acc = fmul2(h[p][0], wo[j * 8]);
            #pragma unroll
            for (int kk = 1; kk < 8; kk++)
                acc = ffma2(h[p][kk], wo[j * 8 + kk], acc);
            float a0, a1; unpack2(acc, a0, a1);
            out[pt * 3 + j] = sigmoid_hw(a0 + a1);
        }
    }
}

extern "C" void kernel_launch(void* const* d_in, const int* in_sizes, int n_in,
                              void* d_out, int out_size) {
    const float* x     = (const float*)d_in[0];
    const float* W_in  = (const float*)d_in[1];
    const float* b_in  = (const float*)d_in[2];
    const float* W_h   = (const float*)d_in[3];
    const float* W_out = (const float*)d_in[4];
    float* out = (float*)d_out;

    void* cw_addr = nullptr;
    cudaGetSymbolAddress(&cw_addr, cW);

    stage_weights<<<(CW_TOTAL + 255) / 256, 256>>>(W_in, b_in, W_h, W_out,
                                                   (float*)cw_addr);

    int n_points = in_sizes[0] / 2;               // x is [N,2]
    int blocks = n_points / PTS_PER_BLOCK;        // 4194304 / 256 = 16384, exact
    mlp_kernel<<<blocks, THREADS>>>(x, out);
}

// round 10
// speedup vs baseline: 1.3265x; 1.1878x over previous
#include <cuda_runtime.h>

typedef unsigned long long u64;

#define THREADS 128
#define NPTS 4                          // points per thread
#define PTS_PER_BLOCK (THREADS * NPTS)
#define HIDDEN 16
#define NLAYERS 8

// ---------- f32x2 packed-math helpers (sm_103a) ----------
__device__ __forceinline__ void unpack2(u64 a, float& lo, float& hi) {
    asm("mov.b64 {%0, %1}, %2;" : "=f"(lo), "=f"(hi) : "l"(a));
}
__device__ __forceinline__ u64 dup2(float s) {  // (s, s)
    u64 r; asm("mov.b64 %0, {%1, %1};" : "=l"(r) : "f"(s)); return r;
}
__device__ __forceinline__ u64 ffma2(u64 a, u64 b, u64 c) {
    u64 d; asm("fma.rn.f32x2 %0, %1, %2, %3;" : "=l"(d) : "l"(a), "l"(b), "l"(c)); return d;
}
__device__ __forceinline__ u64 fmul2(u64 a, u64 b) {
    u64 d; asm("mul.rn.f32x2 %0, %1, %2;" : "=l"(d) : "l"(a), "l"(b)); return d;
}
__device__ __forceinline__ float tanh_hw(float x) {
    float r; asm("tanh.approx.f32 %0, %1;" : "=f"(r) : "f"(x)); return r;
}
__device__ __forceinline__ float sigmoid_hw(float x) {
    // sigmoid(x) = 0.5*tanh(0.5x)+0.5
    return fmaf(tanh_hw(0.5f * x), 0.5f, 0.5f);
}

__global__ void __launch_bounds__(THREADS, 4)
mlp_kernel(const float* __restrict__ x,
           const float* __restrict__ W_in,
           const float* __restrict__ b_in,
           const float* __restrict__ W_h,
           const float* __restrict__ W_out,
           float* __restrict__ out)
{
    // Transposed weights, plain f32 (no lane duplication). u64 reads give
    // natural (W[j][k], W[j+1][k]) output-pairs. All reads are warp-broadcast.
    __shared__ __align__(16) float sWh_t[NLAYERS * HIDDEN * HIDDEN]; // [l][k][j]
    __shared__ __align__(16) float sWin_t[2 * HIDDEN];               // [c][j]
    __shared__ __align__(16) float sBin[HIDDEN];                     // [j]
    __shared__ __align__(16) float sWout_t[HIDDEN * 4];              // [k][j], j=3 pad 0

    const int tid = threadIdx.x;

    #pragma unroll
    for (int i = tid; i < NLAYERS * 256; i += THREADS) {
        int l = i >> 8, r = i & 255, j = r >> 4, k = r & 15;
        sWh_t[(l * 16 + k) * 16 + j] = W_h[i];      // i = l*256 + j*16 + k
    }
    if (tid < 32)      { int j = tid >> 1, c = tid & 1; sWin_t[c * 16 + j] = W_in[j * 2 + c]; }
    else if (tid < 48) { sBin[tid - 32] = b_in[tid - 32]; }
    else if (tid < 112){ int i = tid - 48; int k = i >> 2, j = i & 3;
                         sWout_t[i] = (j < 3) ? W_out[j * 16 + k] : 0.0f; }
    __syncthreads();

    const int base = blockIdx.x * PTS_PER_BLOCK + tid;

    const float2* __restrict__ xp = (const float2*)x;
    float2 xv[NPTS];
    #pragma unroll
    for (int p = 0; p < NPTS; p++) xv[p] = xp[base + p * THREADS];

    // ---- input layer: acc[p][jj] accumulates outputs (2j, 2j+1) ----
    float h[NPTS][HIDDEN];
    {
        const u64* __restrict__ w0 = (const u64*)&sWin_t[0];
        const u64* __restrict__ w1 = (const u64*)&sWin_t[16];
        const u64* __restrict__ bb = (const u64*)&sBin[0];
        #pragma unroll
        for (int p = 0; p < NPTS; p++) {
            u64 x0 = dup2(xv[p].x), x1 = dup2(xv[p].y);
            #pragma unroll
            for (int jj = 0; jj < 8; jj++) {
                u64 a = ffma2(x0, w0[jj], bb[jj]);
                a = ffma2(x1, w1[jj], a);
                float t0, t1; unpack2(a, t0, t1);
                h[p][2 * jj]     = tanh_hw(t0);
                h[p][2 * jj + 1] = tanh_hw(t1);
            }
        }
    }

    // ---- 8 hidden layers ----
    #pragma unroll 1
    for (int l = 0; l < NLAYERS; l++) {
        const float* __restrict__ wl = &sWh_t[l * 256];
        u64 acc[NPTS][8];
        // k = 0
        {
            const u64* __restrict__ wr = (const u64*)wl;
            u64 w[8];
            #pragma unroll
            for (int jj = 0; jj < 8; jj++) w[jj] = wr[jj];
            #pragma unroll
            for (int p = 0; p < NPTS; p++) {
                u64 hd = dup2(h[p][0]);
                #pragma unroll
                for (int jj = 0; jj < 8; jj++) acc[p][jj] = fmul2(hd, w[jj]);
            }
        }
        #pragma unroll
        for (int k = 1; k < HIDDEN; k++) {
            const u64* __restrict__ wr = (const u64*)(wl + k * 16);
            u64 w[8];
            #pragma unroll
            for (int jj = 0; jj < 8; jj++) w[jj] = wr[jj];
            #pragma unroll
            for (int p = 0; p < NPTS; p++) {
                u64 hd = dup2(h[p][k]);
                #pragma unroll
                for (int jj = 0; jj < 8; jj++) acc[p][jj] = ffma2(hd, w[jj], acc[p][jj]);
            }
        }
        #pragma unroll
        for (int p = 0; p < NPTS; p++) {
            #pragma unroll
            for (int jj = 0; jj < 8; jj++) {
                float t0, t1; unpack2(acc[p][jj], t0, t1);
                h[p][2 * jj]     = tanh_hw(t0);
                h[p][2 * jj + 1] = tanh_hw(t1);
            }
        }
    }

    // ---- output layer: 16 -> 3 (padded to 4), sigmoid ----
    float o[NPTS][3];
    {
        u64 acc0[NPTS], acc1[NPTS];
        {
            const u64* __restrict__ wr = (const u64*)&sWout_t[0];
            u64 wa = wr[0], wb = wr[1];
            #pragma unroll
            for (int p = 0; p < NPTS; p++) {
                u64 hd = dup2(h[p][0]);
                acc0[p] = fmul2(hd, wa);
                acc1[p] = fmul2(hd, wb);
            }
        }
        #pragma unroll
        for (int k = 1; k < HIDDEN; k++) {
            const u64* __restrict__ wr = (const u64*)&sWout_t[k * 4];
            u64 wa = wr[0], wb = wr[1];
            #pragma unroll
            for (int p = 0; p < NPTS; p++) {
                u64 hd = dup2(h[p][k]);
                acc0[p] = ffma2(hd, wa, acc0[p]);
                acc1[p] = ffma2(hd, wb, acc1[p]);
            }
        }
        #pragma unroll
        for (int p = 0; p < NPTS; p++) {
            float a0, a1, a2, a3;
            unpack2(acc0[p], a0, a1);
            unpack2(acc1[p], a2, a3);
            o[p][0] = sigmoid_hw(a0);
            o[p][1] = sigmoid_hw(a1);
            o[p][2] = sigmoid_hw(a2);
        }
    }

    #pragma unroll
    for (int p = 0; p < NPTS; p++) {
        int pt = base + p * THREADS;
        out[pt * 3 + 0] = o[p][0];
        out[pt * 3 + 1] = o[p][1];
        out[pt * 3 + 2] = o[p][2];
    }
}

extern "C" void kernel_launch(void* const* d_in, const int* in_sizes, int n_in,
                              void* d_out, int out_size) {
    const float* x     = (const float*)d_in[0];
    const float* W_in  = (const float*)d_in[1];
    const float* b_in  = (const float*)d_in[2];
    const float* W_h   = (const float*)d_in[3];
    const float* W_out = (const float*)d_in[4];
    float* out = (float*)d_out;

    int n_points = in_sizes[0] / 2;               // x is [N,2]
    int blocks = n_points / PTS_PER_BLOCK;        // 4194304 / 512 = 8192, exact
    mlp_kernel<<<blocks, THREADS>>>(x, W_in, b_in, W_h, W_out, out);
}

// round 11
// speedup vs baseline: 1.3298x; 1.0025x over previous
#include <cuda_runtime.h>

typedef unsigned long long u64;

#define THREADS 128
#define NPTS 4                          // points per thread
#define PTS_PER_BLOCK (THREADS * NPTS)
#define HIDDEN 16
#define NLAYERS 8

// ---------- f32x2 packed-math helpers (sm_103a) ----------
__device__ __forceinline__ void unpack2(u64 a, float& lo, float& hi) {
    asm("mov.b64 {%0, %1}, %2;" : "=f"(lo), "=f"(hi) : "l"(a));
}
__device__ __forceinline__ u64 dup2(float s) {  // (s, s)
    u64 r; asm("mov.b64 %0, {%1, %1};" : "=l"(r) : "f"(s)); return r;
}
__device__ __forceinline__ u64 ffma2(u64 a, u64 b, u64 c) {
    u64 d; asm("fma.rn.f32x2 %0, %1, %2, %3;" : "=l"(d) : "l"(a), "l"(b), "l"(c)); return d;
}
__device__ __forceinline__ u64 fmul2(u64 a, u64 b) {
    u64 d; asm("mul.rn.f32x2 %0, %1, %2;" : "=l"(d) : "l"(a), "l"(b)); return d;
}
__device__ __forceinline__ float tanh_hw(float x) {
    float r; asm("tanh.approx.f32 %0, %1;" : "=f"(r) : "f"(x)); return r;
}
__device__ __forceinline__ float sigmoid_hw(float x) {
    // sigmoid(x) = 0.5*tanh(0.5x)+0.5
    return fmaf(tanh_hw(0.5f * x), 0.5f, 0.5f);
}

__global__ void __launch_bounds__(THREADS, 4)
mlp_kernel(const float* __restrict__ x,
           const float* __restrict__ W_in,
           const float* __restrict__ b_in,
           const float* __restrict__ W_h,
           const float* __restrict__ W_out,
           float* __restrict__ out)
{
    // Transposed weights, plain f32. Row k of layer l = 16 contiguous floats
    // = 4 ulonglong2 -> broadcast LDS.128 (conflict-free, floor same as .64).
    __shared__ __align__(16) float sWh_t[NLAYERS * HIDDEN * HIDDEN]; // [l][k][j]
    __shared__ __align__(16) float sWin_t[2 * HIDDEN];               // [c][j]
    __shared__ __align__(16) float sBin[HIDDEN];                     // [j]
    __shared__ __align__(16) float sWout_t[HIDDEN * 4];              // [k][j], j=3 pad 0

    const int tid = threadIdx.x;

    #pragma unroll
    for (int i = tid; i < NLAYERS * 256; i += THREADS) {
        int l = i >> 8, r = i & 255, j = r >> 4, k = r & 15;
        sWh_t[(l * 16 + k) * 16 + j] = W_h[i];      // i = l*256 + j*16 + k
    }
    if (tid < 32)      { int j = tid >> 1, c = tid & 1; sWin_t[c * 16 + j] = W_in[j * 2 + c]; }
    else if (tid < 48) { sBin[tid - 32] = b_in[tid - 32]; }
    else if (tid < 112){ int i = tid - 48; int k = i >> 2, j = i & 3;
                         sWout_t[i] = (j < 3) ? W_out[j * 16 + k] : 0.0f; }
    __syncthreads();

    const int base = blockIdx.x * PTS_PER_BLOCK + tid;

    const float2* __restrict__ xp = (const float2*)x;
    float2 xv[NPTS];
    #pragma unroll
    for (int p = 0; p < NPTS; p++) xv[p] = xp[base + p * THREADS];

    // ---- input layer: acc[p][jj] accumulates outputs (2j, 2j+1) ----
    float h[NPTS][HIDDEN];
    {
        const u64* __restrict__ w0 = (const u64*)&sWin_t[0];
        const u64* __restrict__ w1 = (const u64*)&sWin_t[16];
        const u64* __restrict__ bb = (const u64*)&sBin[0];
        #pragma unroll
        for (int p = 0; p < NPTS; p++) {
            u64 x0 = dup2(xv[p].x), x1 = dup2(xv[p].y);
            #pragma unroll
            for (int jj = 0; jj < 8; jj++) {
                u64 a = ffma2(x0, w0[jj], bb[jj]);
                a = ffma2(x1, w1[jj], a);
                float t0, t1; unpack2(a, t0, t1);
                h[p][2 * jj]     = tanh_hw(t0);
                h[p][2 * jj + 1] = tanh_hw(t1);
            }
        }
    }

    // ---- 8 hidden layers ----
    #pragma unroll 1
    for (int l = 0; l < NLAYERS; l++) {
        const ulonglong2* __restrict__ wl = (const ulonglong2*)&sWh_t[l * 256]; // [k*4 + jj2]
        u64 acc[NPTS][8];
        // k = 0
        {
            u64 w[8];
            #pragma unroll
            for (int jj2 = 0; jj2 < 4; jj2++) {
                ulonglong2 v = wl[jj2];
                w[2 * jj2] = v.x; w[2 * jj2 + 1] = v.y;
            }
            #pragma unroll
            for (int p = 0; p < NPTS; p++) {
                u64 hd = dup2(h[p][0]);
                #pragma unroll
                for (int jj = 0; jj < 8; jj++) acc[p][jj] = fmul2(hd, w[jj]);
            }
        }
        #pragma unroll
        for (int k = 1; k < HIDDEN; k++) {
            u64 w[8];
            #pragma unroll
            for (int jj2 = 0; jj2 < 4; jj2++) {
                ulonglong2 v = wl[k * 4 + jj2];
                w[2 * jj2] = v.x; w[2 * jj2 + 1] = v.y;
            }
            #pragma unroll
            for (int p = 0; p < NPTS; p++) {
                u64 hd = dup2(h[p][k]);
                #pragma unroll
                for (int jj = 0; jj < 8; jj++) acc[p][jj] = ffma2(hd, w[jj], acc[p][jj]);
            }
        }
        #pragma unroll
        for (int p = 0; p < NPTS; p++) {
            #pragma unroll
            for (int jj = 0; jj < 8; jj++) {
                float t0, t1; unpack2(acc[p][jj], t0, t1);
                h[p][2 * jj]     = tanh_hw(t0);
                h[p][2 * jj + 1] = tanh_hw(t1);
            }
        }
    }

    // ---- output layer: 16 -> 3 (padded to 4), sigmoid ----
    float o[NPTS][3];
    {
        u64 acc0[NPTS], acc1[NPTS];
        {
            ulonglong2 v = *(const ulonglong2*)&sWout_t[0];
            #pragma unroll
            for (int p = 0; p < NPTS; p++) {
                u64 hd = dup2(h[p][0]);
                acc0[p] = fmul2(hd, v.x);
                acc1[p] = fmul2(hd, v.y);
            }
        }
        #pragma unroll
        for (int k = 1; k < HIDDEN; k++) {
            ulonglong2 v = *(const ulonglong2*)&sWout_t[k * 4];
            #pragma unroll
            for (int p = 0; p < NPTS; p++) {
                u64 hd = dup2(h[p][k]);
                acc0[p] = ffma2(hd, v.x, acc0[p]);
                acc1[p] = ffma2(hd, v.y, acc1[p]);
            }
        }
        #pragma unroll
        for (int p = 0; p < NPTS; p++) {
            float a0, a1, a2, a3;
            unpack2(acc0[p], a0, a1);
            unpack2(acc1[p], a2, a3);
            o[p][0] = sigmoid_hw(a0);
            o[p][1] = sigmoid_hw(a1);
            o[p][2] = sigmoid_hw(a2);
        }
    }

    #pragma unroll
    for (int p = 0; p < NPTS; p++) {
        int pt = base + p * THREADS;
        out[pt * 3 + 0] = o[p][0];
        out[pt * 3 + 1] = o[p][1];
        out[pt * 3 + 2] = o[p][2];
    }
}

extern "C" void kernel_launch(void* const* d_in, const int* in_sizes, int n_in,
                              void* d_out, int out_size) {
    const float* x     = (const float*)d_in[0];
    const float* W_in  = (const float*)d_in[1];
    const float* b_in  = (const float*)d_in[2];
    const float* W_h   = (const float*)d_in[3];
    const float* W_out = (const float*)d_in[4];
    float* out = (float*)d_out;

    int n_points = in_sizes[0] / 2;               // x is [N,2]
    int blocks = n_points / PTS_PER_BLOCK;        // 4194304 / 512 = 8192, exact
    mlp_kernel<<<blocks, THREADS>>>(x, W_in, b_in, W_h, W_out, out);
}